// round 1
// baseline (speedup 1.0000x reference)
#include <cuda_runtime.h>
#include <math.h>

#define Bq 64
#define Sq 384
#define Eq 64
#define Dq 50
#define Gq 256   // 4*E

// scratch (allocation-free rule: __device__ globals)
__device__ float g_h1[Bq*Sq*Eq];
__device__ float g_c1[Bq*Sq*Eq];
__device__ float g_out[Bq*Sq*Eq];
__device__ float g_base[Bq*Sq*Eq];
__device__ float g_Rt[Bq*Sq*Eq];

__device__ __forceinline__ float sigf(float x){ return 1.f/(1.f + expf(-x)); }

// ---------------------------------------------------------------------------
// LSTM: one CTA per batch element, 256 threads (one per gate row).
// Weights live in registers (50 + 64 floats per thread); x and h are
// broadcast from shared memory. mode 0: zero init, writes g_h1/g_c1.
// mode 1: per-element gathered init from (g_h1,g_c1) at iidx, writes g_out.
// ---------------------------------------------------------------------------
__global__ __launch_bounds__(256) void lstm_kernel(
    const int* __restrict__ tokens, const float* __restrict__ emb,
    const float* __restrict__ Wih, const float* __restrict__ Whh,
    const float* __restrict__ bih, const float* __restrict__ bhh,
    const int* __restrict__ iidx, int mode)
{
    __shared__ float xs[3][Dq];
    __shared__ float hs[Eq];
    __shared__ float gs[Gq];
    __shared__ int   toks[Sq];

    int b = blockIdx.x, j = threadIdx.x;

    float* oh = mode ? g_out : g_h1;
    float* oc = mode ? nullptr : g_c1;

    float wih[Dq], whh[Eq];
#pragma unroll
    for (int k = 0; k < Dq; k++) wih[k] = Wih[j*Dq + k];
#pragma unroll
    for (int k = 0; k < Eq; k++) whh[k] = Whh[j*Eq + k];
    float bias = bih[j] + bhh[j];

    for (int t = j; t < Sq; t += 256) toks[t] = tokens[b*Sq + t];

    float c = 0.f;
    if (j < Eq) {
        float h0 = 0.f;
        if (mode) {
            int idx = iidx[b*Eq + j];          // s1_len is (B,1,E)
            h0 = g_h1[(b*Sq + idx)*Eq + j];
            c  = g_c1[(b*Sq + idx)*Eq + j];
        }
        hs[j] = h0;
    }
    __syncthreads();
    if (j < Dq) {
        xs[0][j] = emb[toks[0]*Dq + j];
        xs[1][j] = emb[toks[1]*Dq + j];
    }
    __syncthreads();

    for (int t = 0; t < Sq; t++) {
        // prefetch embedding row for t+2
        if (j >= 128 && j < 128 + Dq && t + 2 < Sq)
            xs[(t+2)%3][j-128] = emb[toks[t+2]*Dq + (j-128)];

        const float* x = xs[t%3];
        float acc = bias;
#pragma unroll
        for (int k = 0; k < Dq; k++) acc += wih[k]*x[k];
#pragma unroll
        for (int k = 0; k < Eq; k++) acc += whh[k]*hs[k];
        gs[j] = acc;
        __syncthreads();

        if (j < Eq) {
            float ig = sigf(gs[j]);
            float fg = sigf(gs[Eq + j]);
            float gg = tanhf(gs[2*Eq + j]);
            float og = sigf(gs[3*Eq + j]);
            c = fg*c + ig*gg;
            float h = og*tanhf(c);
            hs[j] = h;
            oh[(b*Sq + t)*Eq + j] = h;
            if (oc) oc[(b*Sq + t)*Eq + j] = c;
        }
        __syncthreads();
    }
}

// ---------------------------------------------------------------------------
// base[b,s,:] = h1[b,s,:] @ wy + out[b,s,:] @ wh
// grid (24, B), 16 s-rows per block, 256 threads (16 s x 16 groups of 4 e)
// ---------------------------------------------------------------------------
__global__ __launch_bounds__(256) void base_kernel(
    const float* __restrict__ wy, const float* __restrict__ wh)
{
    __shared__ float wys[Eq*Eq], whs[Eq*Eq];
    __shared__ float ht[16][Eq], ot[16][Eq];

    int b  = blockIdx.y;
    int s0 = blockIdx.x * 16;
    int tid = threadIdx.x;

    for (int i = tid; i < Eq*Eq; i += 256) { wys[i] = wy[i]; whs[i] = wh[i]; }
    for (int i = tid; i < 16*Eq; i += 256) {
        int s = i >> 6, k = i & 63;
        ht[s][k] = g_h1 [(b*Sq + s0 + s)*Eq + k];
        ot[s][k] = g_out[(b*Sq + s0 + s)*Eq + k];
    }
    __syncthreads();

    int sl = tid >> 4;          // 0..15
    int e0 = (tid & 15) * 4;    // 0..60
    float acc[4] = {0.f, 0.f, 0.f, 0.f};
#pragma unroll 8
    for (int k = 0; k < Eq; k++) {
        float hv = ht[sl][k], ov = ot[sl][k];
#pragma unroll
        for (int u = 0; u < 4; u++)
            acc[u] += hv*wys[k*Eq + e0 + u] + ov*whs[k*Eq + e0 + u];
    }
    float* dst = &g_base[(b*Sq + s0 + sl)*Eq + e0];
#pragma unroll
    for (int u = 0; u < 4; u++) dst[u] = acc[u];
}

// ---------------------------------------------------------------------------
// Attention scan: one CTA per b, 384 threads (one per s).
// base[b] and h1[b] staged in dynamic smem with row stride 65 (bank-safe).
// Softmax without max-subtraction: |score| <= sum|w| ~ 51, exp in range.
// ---------------------------------------------------------------------------
#define ATT_SMEM ((2*Sq*65 + 4*64 + 3*Sq + 16)*4)

__global__ __launch_bounds__(384) void attn_kernel(
    const float* __restrict__ wvec, const float* __restrict__ wr,
    const float* __restrict__ wt,   const float* __restrict__ s1s)
{
    extern __shared__ float sm[];
    float* base_s = sm;                   // Sq*65
    float* h_sm   = base_s + Sq*65;       // Sq*65
    float* r_s    = h_sm + Sq*65;         // 64
    float* rwr_s  = r_s + 64;             // 64
    float* trwt_s = rwr_s + 64;           // 64
    float* w_s    = trwt_s + 64;          // 64
    float* s1s_s  = w_s + 64;             // Sq
    float* p_s    = s1s_s + Sq;           // Sq
    float* part   = p_s + Sq;             // Sq
    float* red    = part + Sq;            // 16

    int b = blockIdx.x, tid = threadIdx.x;
    int lane = tid & 31, wid = tid >> 5;

    for (int i = tid; i < Sq*Eq; i += 384) {
        int s = i >> 6, e = i & 63;
        base_s[s*65 + e] = g_base[b*Sq*Eq + i];
        h_sm  [s*65 + e] = g_h1 [b*Sq*Eq + i];
    }
    if (tid < 64) { r_s[tid] = 0.f; w_s[tid] = wvec[tid]; }
    s1s_s[tid] = s1s[b*Sq + tid];
    __syncthreads();

    for (int t = 0; t < Sq; t++) {
        if (tid < 64) {
            float a = 0.f;
#pragma unroll 8
            for (int k = 0; k < Eq; k++) a += r_s[k]*wr[k*Eq + tid];
            rwr_s[tid] = a;
        } else if (tid < 128) {
            int e = tid - 64;
            float a = 0.f;
#pragma unroll 8
            for (int k = 0; k < Eq; k++) a += r_s[k]*wt[k*Eq + e];
            trwt_s[e] = tanhf(a);
        }
        __syncthreads();

        // score + exp (thread tid owns row s = tid)
        float p;
        {
            float sc = 0.f;
            const float* brow = &base_s[tid*65];
#pragma unroll 8
            for (int e = 0; e < Eq; e++)
                sc += w_s[e]*tanhf(brow[e] + rwr_s[e]);
            float m1 = s1s_s[tid];
            sc = m1*sc - (1.f - m1)*1e12f;
            p = expf(sc);
            p_s[tid] = p;
        }
        // block sum of p
        float v = p;
#pragma unroll
        for (int o = 16; o > 0; o >>= 1) v += __shfl_xor_sync(0xffffffffu, v, o);
        if (lane == 0) red[wid] = v;
        __syncthreads();
        if (tid == 0) {
            float s = 0.f;
#pragma unroll
            for (int i = 0; i < 12; i++) s += red[i];
            red[12] = 1.f/s;
        }
        __syncthreads();
        float invden = red[12];

        // r_new[e] = (sum_s h[s,e]*p[s]) * invden + tanh(r@wt)[e]
        {
            int e = tid & 63, grp = tid >> 6;
            float a = 0.f;
            int sb = grp*64;
#pragma unroll 8
            for (int si = 0; si < 64; si++)
                a += h_sm[(sb + si)*65 + e] * p_s[sb + si];
            part[tid] = a;
        }
        __syncthreads();
        if (tid < 64) {
            float a = part[tid] + part[64+tid] + part[128+tid]
                    + part[192+tid] + part[256+tid] + part[320+tid];
            float rn = a*invden + trwt_s[tid];
            r_s[tid] = rn;
            g_Rt[(b*Sq + t)*Eq + tid] = rn;
        }
        __syncthreads();
    }
}

// ---------------------------------------------------------------------------
// Final gathers + MLP head
// ---------------------------------------------------------------------------
__global__ __launch_bounds__(128) void final_kernel(
    const int* __restrict__ s2len,
    const float* __restrict__ wp, const float* __restrict__ wx,
    const float* __restrict__ l1W, const float* __restrict__ l1b,
    const float* __restrict__ lW,  const float* __restrict__ lb,
    float* __restrict__ outp)
{
    __shared__ float rn[64], hn[64], hid[64], h2[128];
    int b = blockIdx.x, tid = threadIdx.x;

    if (tid < 64) {
        int idx = s2len[b*64 + tid];
        rn[tid] = g_Rt [(b*Sq + idx)*Eq + tid];
        hn[tid] = g_out[(b*Sq + idx)*Eq + tid];
    }
    __syncthreads();
    if (tid < 64) {
        float a = 0.f;
#pragma unroll 8
        for (int e = 0; e < 64; e++)
            a += rn[e]*wp[e*64 + tid] + hn[e]*wx[e*64 + tid];
        hid[tid] = tanhf(a);
    }
    __syncthreads();
    {
        float a = l1b[tid];
#pragma unroll 8
        for (int f = 0; f < 64; f++) a += hid[f]*l1W[tid*64 + f];
        h2[tid] = tanhf(a);
    }
    __syncthreads();
    if (tid < 4) {
        float a = lb[tid];
#pragma unroll 8
        for (int j = 0; j < 128; j++) a += h2[j]*lW[tid*128 + j];
        outp[b*4 + tid] = a;
    }
}

// ---------------------------------------------------------------------------
extern "C" void kernel_launch(void* const* d_in, const int* in_sizes, int n_in,
                              void* d_out, int out_size)
{
    (void)in_sizes; (void)n_in; (void)out_size;

    const int*   s1   = (const int*)d_in[0];
    const int*   s2   = (const int*)d_in[1];
    const int*   s1l  = (const int*)d_in[2];
    const int*   s2l  = (const int*)d_in[3];
    const float* s1s  = (const float*)d_in[4];
    /* d_in[5] = s2_s, unused by the reference */
    const float* emb  = (const float*)d_in[6];
    const float* Wih1 = (const float*)d_in[7];
    const float* Whh1 = (const float*)d_in[8];
    const float* bih1 = (const float*)d_in[9];
    const float* bhh1 = (const float*)d_in[10];
    const float* Wih2 = (const float*)d_in[11];
    const float* Whh2 = (const float*)d_in[12];
    const float* bih2 = (const float*)d_in[13];
    const float* bhh2 = (const float*)d_in[14];
    const float* wy   = (const float*)d_in[15];
    const float* wh   = (const float*)d_in[16];
    const float* wv   = (const float*)d_in[17];
    const float* wp   = (const float*)d_in[18];
    const float* wx   = (const float*)d_in[19];
    const float* wr   = (const float*)d_in[20];
    const float* wt   = (const float*)d_in[21];
    const float* l1W  = (const float*)d_in[22];
    const float* l1b  = (const float*)d_in[23];
    const float* lW   = (const float*)d_in[24];
    const float* lb   = (const float*)d_in[25];
    float* outp = (float*)d_out;

    cudaFuncSetAttribute(attn_kernel,
                         cudaFuncAttributeMaxDynamicSharedMemorySize, ATT_SMEM);

    lstm_kernel<<<Bq, 256>>>(s1, emb, Wih1, Whh1, bih1, bhh1, nullptr, 0);
    lstm_kernel<<<Bq, 256>>>(s2, emb, Wih2, Whh2, bih2, bhh2, s1l, 1);
    base_kernel<<<dim3(24, Bq), 256>>>(wy, wh);
    attn_kernel<<<Bq, 384, ATT_SMEM>>>(wv, wr, wt, s1s);
    final_kernel<<<Bq, 128>>>(s2l, wp, wx, l1W, l1b, lW, lb, outp);
}

// round 2
// speedup vs baseline: 1.0880x; 1.0880x over previous
#include <cuda_runtime.h>
#include <math.h>

#define Bq 64
#define Sq 384
#define Eq 64
#define Dq 50
#define Gq 256   // 4*E

// scratch (allocation-free rule: __device__ globals)
__device__ float g_h1[Bq*Sq*Eq];
__device__ float g_c1[Bq*Sq*Eq];
__device__ float g_out[Bq*Sq*Eq];
__device__ float g_base[Bq*Sq*Eq];
__device__ float g_Rt[Bq*Sq*Eq];
__device__ float g_xp1[Bq*Sq*Gq];
__device__ float g_xp2[Bq*Sq*Gq];

// ---- fast transcendentals (err ~1e-6, well under the 1e-3 gate) ----------
__device__ __forceinline__ float rcp_fast(float x){
    float r; asm("rcp.approx.f32 %0, %1;" : "=f"(r) : "f"(x)); return r;
}
__device__ __forceinline__ float ftanh(float x){
    float t = __expf(-2.f * fabsf(x));        // FMUL + MUFU.EX2
    float y = (1.f - t) * rcp_fast(1.f + t);  // FADD,FADD,MUFU.RCP,FMUL
    return copysignf(y, x);                   // LOP3
}
__device__ __forceinline__ float fsig(float x){
    return rcp_fast(1.f + __expf(-x));
}

// ---------------------------------------------------------------------------
// Input projection (loop-invariant part of the LSTM):
// xp[b,s,g] = emb[tok[b,s]] @ Wih[g,:] + bih[g] + bhh[g]
// 32 (b,s) rows per CTA, 256 threads (one per gate).
// ---------------------------------------------------------------------------
__global__ __launch_bounds__(256) void xproj_kernel(
    const int* __restrict__ toks, const float* __restrict__ emb,
    const float* __restrict__ Wih, const float* __restrict__ bih,
    const float* __restrict__ bhh, float* __restrict__ xp)
{
    __shared__ float xs[32][Dq];
    __shared__ int   tk[32];
    int row0 = blockIdx.x * 32;
    int j = threadIdx.x;

    if (j < 32) tk[j] = toks[row0 + j];
    __syncthreads();
    for (int i = j; i < 32*Dq; i += 256) {
        int r = i / Dq, k = i % Dq;
        xs[r][k] = emb[tk[r]*Dq + k];
    }

    float w[Dq];
#pragma unroll
    for (int k = 0; k < Dq; k++) w[k] = Wih[j*Dq + k];
    float bias = bih[j] + bhh[j];
    __syncthreads();

#pragma unroll 4
    for (int r = 0; r < 32; r++) {
        float acc = bias;
#pragma unroll
        for (int k = 0; k < Dq; k++) acc += w[k]*xs[r][k];
        xp[(row0 + r)*Gq + j] = acc;
    }
}

// ---------------------------------------------------------------------------
// Recurrent LSTM: one CTA per batch element, 256 threads (one per gate).
// Gate preactivation = precomputed xp (prefetched one step ahead) + h@Whh.
// ---------------------------------------------------------------------------
__global__ __launch_bounds__(256) void lstm_kernel(
    const float* __restrict__ xp, const float* __restrict__ Whh,
    const int* __restrict__ iidx, int mode)
{
    __shared__ float hs[Eq];
    __shared__ float gs[Gq];

    int b = blockIdx.x, j = threadIdx.x;
    float* oh = mode ? g_out : g_h1;
    float* oc = mode ? nullptr : g_c1;

    float whh[Eq];
#pragma unroll
    for (int k = 0; k < Eq; k++) whh[k] = Whh[j*Eq + k];

    float c = 0.f;
    if (j < Eq) {
        float h0 = 0.f;
        if (mode) {
            int idx = iidx[b*Eq + j];          // s1_len is (B,1,E)
            h0 = g_h1[(b*Sq + idx)*Eq + j];
            c  = g_c1[(b*Sq + idx)*Eq + j];
        }
        hs[j] = h0;
    }
    __syncthreads();

    const float* xpb = xp + (size_t)b*Sq*Gq + j;
    float xv = xpb[0];

    for (int t = 0; t < Sq; t++) {
        float acc = xv;
        const float4* h4 = (const float4*)hs;
#pragma unroll
        for (int k = 0; k < Eq/4; k++) {
            float4 hv = h4[k];
            acc += whh[4*k]*hv.x + whh[4*k+1]*hv.y
                 + whh[4*k+2]*hv.z + whh[4*k+3]*hv.w;
        }
        if (t + 1 < Sq) xv = xpb[(t+1)*Gq];    // prefetch next gate input
        gs[j] = acc;
        __syncthreads();

        if (j < Eq) {
            float ig = fsig(gs[j]);
            float fg = fsig(gs[Eq + j]);
            float gg = ftanh(gs[2*Eq + j]);
            float og = fsig(gs[3*Eq + j]);
            c = fg*c + ig*gg;
            float h = og*ftanh(c);
            hs[j] = h;
            oh[(b*Sq + t)*Eq + j] = h;
            if (oc) oc[(b*Sq + t)*Eq + j] = c;
        }
        __syncthreads();
    }
}

// ---------------------------------------------------------------------------
// base[b,s,:] = h1[b,s,:] @ wy + out[b,s,:] @ wh
// ---------------------------------------------------------------------------
__global__ __launch_bounds__(256) void base_kernel(
    const float* __restrict__ wy, const float* __restrict__ wh)
{
    __shared__ float wys[Eq*Eq], whs[Eq*Eq];
    __shared__ float ht[16][Eq], ot[16][Eq];

    int b  = blockIdx.y;
    int s0 = blockIdx.x * 16;
    int tid = threadIdx.x;

    for (int i = tid; i < Eq*Eq; i += 256) { wys[i] = wy[i]; whs[i] = wh[i]; }
    for (int i = tid; i < 16*Eq; i += 256) {
        int s = i >> 6, k = i & 63;
        ht[s][k] = g_h1 [(b*Sq + s0 + s)*Eq + k];
        ot[s][k] = g_out[(b*Sq + s0 + s)*Eq + k];
    }
    __syncthreads();

    int sl = tid >> 4;
    int e0 = (tid & 15) * 4;
    float acc[4] = {0.f, 0.f, 0.f, 0.f};
#pragma unroll 8
    for (int k = 0; k < Eq; k++) {
        float hv = ht[sl][k], ov = ot[sl][k];
#pragma unroll
        for (int u = 0; u < 4; u++)
            acc[u] += hv*wys[k*Eq + e0 + u] + ov*whs[k*Eq + e0 + u];
    }
    float* dst = &g_base[(b*Sq + s0 + sl)*Eq + e0];
#pragma unroll
    for (int u = 0; u < 4; u++) dst[u] = acc[u];
}

// ---------------------------------------------------------------------------
// Attention scan: one CTA per b, 384 threads (one per s).
// base[b] and h1[b] staged in smem with row stride 65 (bank-safe).
// Softmax without max-subtraction: |score| <= sum|w| ~ 51, exp in fp32 range.
// ---------------------------------------------------------------------------
#define ATT_SMEM ((2*Sq*65 + 4*64 + 3*Sq + 16)*4)

__global__ __launch_bounds__(384) void attn_kernel(
    const float* __restrict__ wvec, const float* __restrict__ wr,
    const float* __restrict__ wt,   const float* __restrict__ s1s)
{
    extern __shared__ float sm[];
    float* base_s = sm;                   // Sq*65
    float* h_sm   = base_s + Sq*65;       // Sq*65
    float* r_s    = h_sm + Sq*65;         // 64
    float* rwr_s  = r_s + 64;             // 64
    float* trwt_s = rwr_s + 64;           // 64
    float* w_s    = trwt_s + 64;          // 64
    float* s1s_s  = w_s + 64;             // Sq
    float* p_s    = s1s_s + Sq;           // Sq
    float* part   = p_s + Sq;             // Sq
    float* red    = part + Sq;            // 16

    int b = blockIdx.x, tid = threadIdx.x;
    int lane = tid & 31, wid = tid >> 5;

    for (int i = tid; i < Sq*Eq; i += 384) {
        int s = i >> 6, e = i & 63;
        base_s[s*65 + e] = g_base[b*Sq*Eq + i];
        h_sm  [s*65 + e] = g_h1 [b*Sq*Eq + i];
    }
    if (tid < 64) { r_s[tid] = 0.f; w_s[tid] = wvec[tid]; }
    s1s_s[tid] = s1s[b*Sq + tid];
    __syncthreads();

    for (int t = 0; t < Sq; t++) {
        if (tid < 64) {
            float a = 0.f;
#pragma unroll 8
            for (int k = 0; k < Eq; k++) a += r_s[k]*wr[k*Eq + tid];
            rwr_s[tid] = a;
        } else if (tid < 128) {
            int e = tid - 64;
            float a = 0.f;
#pragma unroll 8
            for (int k = 0; k < Eq; k++) a += r_s[k]*wt[k*Eq + e];
            trwt_s[e] = ftanh(a);
        }
        __syncthreads();

        // score + exp (thread tid owns row s = tid)
        float p;
        {
            float sc = 0.f;
            const float* brow = &base_s[tid*65];
#pragma unroll 8
            for (int e = 0; e < Eq; e++)
                sc += w_s[e]*ftanh(brow[e] + rwr_s[e]);
            float m1 = s1s_s[tid];
            sc = m1*sc - (1.f - m1)*1e12f;
            p = __expf(sc);
            p_s[tid] = p;
        }
        // block sum of p
        float v = p;
#pragma unroll
        for (int o = 16; o > 0; o >>= 1) v += __shfl_xor_sync(0xffffffffu, v, o);
        if (lane == 0) red[wid] = v;
        __syncthreads();
        if (tid == 0) {
            float s = 0.f;
#pragma unroll
            for (int i = 0; i < 12; i++) s += red[i];
            red[12] = rcp_fast(s);
        }
        __syncthreads();
        float invden = red[12];

        // r_new[e] = (sum_s h[s,e]*p[s]) * invden + tanh(r@wt)[e]
        {
            int e = tid & 63, grp = tid >> 6;
            float a = 0.f;
            int sb = grp*64;
#pragma unroll 8
            for (int si = 0; si < 64; si++)
                a += h_sm[(sb + si)*65 + e] * p_s[sb + si];
            part[tid] = a;
        }
        __syncthreads();
        if (tid < 64) {
            float a = part[tid] + part[64+tid] + part[128+tid]
                    + part[192+tid] + part[256+tid] + part[320+tid];
            float rn = a*invden + trwt_s[tid];
            r_s[tid] = rn;
            g_Rt[(b*Sq + t)*Eq + tid] = rn;
        }
        __syncthreads();
    }
}

// ---------------------------------------------------------------------------
// Final gathers + MLP head
// ---------------------------------------------------------------------------
__global__ __launch_bounds__(128) void final_kernel(
    const int* __restrict__ s2len,
    const float* __restrict__ wp, const float* __restrict__ wx,
    const float* __restrict__ l1W, const float* __restrict__ l1b,
    const float* __restrict__ lW,  const float* __restrict__ lb,
    float* __restrict__ outp)
{
    __shared__ float rn[64], hn[64], hid[64], h2[128];
    int b = blockIdx.x, tid = threadIdx.x;

    if (tid < 64) {
        int idx = s2len[b*64 + tid];
        rn[tid] = g_Rt [(b*Sq + idx)*Eq + tid];
        hn[tid] = g_out[(b*Sq + idx)*Eq + tid];
    }
    __syncthreads();
    if (tid < 64) {
        float a = 0.f;
#pragma unroll 8
        for (int e = 0; e < 64; e++)
            a += rn[e]*wp[e*64 + tid] + hn[e]*wx[e*64 + tid];
        hid[tid] = ftanh(a);
    }
    __syncthreads();
    {
        float a = l1b[tid];
#pragma unroll 8
        for (int f = 0; f < 64; f++) a += hid[f]*l1W[tid*64 + f];
        h2[tid] = ftanh(a);
    }
    __syncthreads();
    if (tid < 4) {
        float a = lb[tid];
#pragma unroll 8
        for (int j = 0; j < 128; j++) a += h2[j]*lW[tid*128 + j];
        outp[b*4 + tid] = a;
    }
}

// ---------------------------------------------------------------------------
extern "C" void kernel_launch(void* const* d_in, const int* in_sizes, int n_in,
                              void* d_out, int out_size)
{
    (void)in_sizes; (void)n_in; (void)out_size;

    const int*   s1   = (const int*)d_in[0];
    const int*   s2   = (const int*)d_in[1];
    const int*   s1l  = (const int*)d_in[2];
    const int*   s2l  = (const int*)d_in[3];
    const float* s1s  = (const float*)d_in[4];
    /* d_in[5] = s2_s, unused by the reference */
    const float* emb  = (const float*)d_in[6];
    const float* Wih1 = (const float*)d_in[7];
    const float* Whh1 = (const float*)d_in[8];
    const float* bih1 = (const float*)d_in[9];
    const float* bhh1 = (const float*)d_in[10];
    const float* Wih2 = (const float*)d_in[11];
    const float* Whh2 = (const float*)d_in[12];
    const float* bih2 = (const float*)d_in[13];
    const float* bhh2 = (const float*)d_in[14];
    const float* wy   = (const float*)d_in[15];
    const float* wh   = (const float*)d_in[16];
    const float* wv   = (const float*)d_in[17];
    const float* wp   = (const float*)d_in[18];
    const float* wx   = (const float*)d_in[19];
    const float* wr   = (const float*)d_in[20];
    const float* wt   = (const float*)d_in[21];
    const float* l1W  = (const float*)d_in[22];
    const float* l1b  = (const float*)d_in[23];
    const float* lW   = (const float*)d_in[24];
    const float* lb   = (const float*)d_in[25];
    float* outp = (float*)d_out;

    cudaFuncSetAttribute(attn_kernel,
                         cudaFuncAttributeMaxDynamicSharedMemorySize, ATT_SMEM);

    float* xp1; cudaGetSymbolAddress((void**)&xp1, g_xp1);
    float* xp2; cudaGetSymbolAddress((void**)&xp2, g_xp2);

    xproj_kernel<<<(Bq*Sq)/32, 256>>>(s1, emb, Wih1, bih1, bhh1, xp1);
    xproj_kernel<<<(Bq*Sq)/32, 256>>>(s2, emb, Wih2, bih2, bhh2, xp2);
    lstm_kernel<<<Bq, 256>>>(xp1, Whh1, nullptr, 0);
    lstm_kernel<<<Bq, 256>>>(xp2, Whh2, s1l, 1);
    base_kernel<<<dim3(24, Bq), 256>>>(wy, wh);
    attn_kernel<<<Bq, 384, ATT_SMEM>>>(wv, wr, wt, s1s);
    final_kernel<<<Bq, 128>>>(s2l, wp, wx, l1W, l1b, lW, lb, outp);
}

// round 3
// speedup vs baseline: 1.6476x; 1.5144x over previous
#include <cuda_runtime.h>
#include <math.h>

#define Bq 64
#define Sq 384
#define Eq 64
#define Dq 50
#define Gq 256   // 4*E
#define ST 68    // smem row stride (16B-aligned rows, conflict-free)

// scratch (allocation-free rule: __device__ globals)
__device__ float g_h1[Bq*Sq*Eq];
__device__ float g_c1[Bq*Sq*Eq];
__device__ float g_out[Bq*Sq*Eq];
__device__ float g_base[Bq*Sq*Eq];
__device__ float g_Rt[Bq*Sq*Eq];
__device__ float g_xp1[Bq*Sq*Gq];
__device__ float g_xp2[Bq*Sq*Gq];

// ---- fast transcendentals (err ~1e-6, well under the 1e-3 gate) ----------
__device__ __forceinline__ float rcp_fast(float x){
    float r; asm("rcp.approx.f32 %0, %1;" : "=f"(r) : "f"(x)); return r;
}
__device__ __forceinline__ float ftanh(float x){
    float t = __expf(-2.f * fabsf(x));
    float y = (1.f - t) * rcp_fast(1.f + t);
    return copysignf(y, x);
}
__device__ __forceinline__ float fsig(float x){
    return rcp_fast(1.f + __expf(-x));
}

// ---------------------------------------------------------------------------
// Input projection: xp[b,s,g] = emb[tok[b,s]] @ Wih[g,:] + bih[g] + bhh[g]
// ---------------------------------------------------------------------------
__global__ __launch_bounds__(256) void xproj_kernel(
    const int* __restrict__ toks, const float* __restrict__ emb,
    const float* __restrict__ Wih, const float* __restrict__ bih,
    const float* __restrict__ bhh, float* __restrict__ xp)
{
    __shared__ float xs[32][Dq];
    __shared__ int   tk[32];
    int row0 = blockIdx.x * 32;
    int j = threadIdx.x;

    if (j < 32) tk[j] = toks[row0 + j];
    __syncthreads();
    for (int i = j; i < 32*Dq; i += 256) {
        int r = i / Dq, k = i % Dq;
        xs[r][k] = emb[tk[r]*Dq + k];
    }

    float w[Dq];
#pragma unroll
    for (int k = 0; k < Dq; k++) w[k] = Wih[j*Dq + k];
    float bias = bih[j] + bhh[j];
    __syncthreads();

#pragma unroll 4
    for (int r = 0; r < 32; r++) {
        float acc = bias;
#pragma unroll
        for (int k = 0; k < Dq; k++) acc += w[k]*xs[r][k];
        xp[(row0 + r)*Gq + j] = acc;
    }
}

// ---------------------------------------------------------------------------
// Recurrent LSTM: one CTA per b, 512 threads = 256 gates x 2 halves.
// Each thread does 32 of the 64 recurrent MACs; shfl_xor(1) combines halves.
// ---------------------------------------------------------------------------
__global__ __launch_bounds__(512) void lstm_kernel(
    const float* __restrict__ xp, const float* __restrict__ Whh,
    const int* __restrict__ iidx, int mode)
{
    __shared__ __align__(16) float hs[Eq];
    __shared__ float gs[Gq];

    int b = blockIdx.x, tid = threadIdx.x;
    int g = tid >> 1, half = tid & 1;
    float* oh = mode ? g_out : g_h1;
    float* oc = mode ? nullptr : g_c1;

    float whh[32];
#pragma unroll
    for (int k = 0; k < 32; k++) whh[k] = Whh[g*Eq + half*32 + k];

    float c = 0.f;
    if (tid < Eq) {
        float h0 = 0.f;
        if (mode) {
            int idx = iidx[b*Eq + tid];        // s1_len is (B,1,E)
            h0 = g_h1[(b*Sq + idx)*Eq + tid];
            c  = g_c1[(b*Sq + idx)*Eq + tid];
        }
        hs[tid] = h0;
    }
    __syncthreads();

    const float* xpb = xp + (size_t)b*Sq*Gq + g;
    float xv = (half == 0) ? xpb[0] : 0.f;

    for (int t = 0; t < Sq; t++) {
        const float4* h4 = (const float4*)(hs + half*32);
        float a0 = 0.f, a1 = 0.f, a2 = 0.f, a3 = 0.f;
#pragma unroll
        for (int k = 0; k < 8; k += 4) {
            float4 v0 = h4[k],   v1 = h4[k+1], v2 = h4[k+2], v3 = h4[k+3];
            a0 += whh[4*k   ]*v0.x + whh[4*k+1 ]*v0.y + whh[4*k+2 ]*v0.z + whh[4*k+3 ]*v0.w;
            a1 += whh[4*k+4 ]*v1.x + whh[4*k+5 ]*v1.y + whh[4*k+6 ]*v1.z + whh[4*k+7 ]*v1.w;
            a2 += whh[4*k+8 ]*v2.x + whh[4*k+9 ]*v2.y + whh[4*k+10]*v2.z + whh[4*k+11]*v2.w;
            a3 += whh[4*k+12]*v3.x + whh[4*k+13]*v3.y + whh[4*k+14]*v3.z + whh[4*k+15]*v3.w;
        }
        float acc = (a0 + a1) + (a2 + a3) + xv;
        acc += __shfl_xor_sync(0xffffffffu, acc, 1);
        if (half == 0) {
            gs[g] = acc;
            if (t + 1 < Sq) xv = xpb[(t+1)*Gq];   // prefetch next gate input
        }
        __syncthreads();

        if (tid < Eq) {
            float ig = fsig(gs[tid]);
            float fg = fsig(gs[Eq + tid]);
            float gg = ftanh(gs[2*Eq + tid]);
            float og = fsig(gs[3*Eq + tid]);
            c = fg*c + ig*gg;
            float h = og*ftanh(c);
            hs[tid] = h;
            oh[(b*Sq + t)*Eq + tid] = h;
            if (oc) oc[(b*Sq + t)*Eq + tid] = c;
        }
        __syncthreads();
    }
}

// ---------------------------------------------------------------------------
// base[b,s,:] = h1[b,s,:] @ wy + out[b,s,:] @ wh
// ---------------------------------------------------------------------------
__global__ __launch_bounds__(256) void base_kernel(
    const float* __restrict__ wy, const float* __restrict__ wh)
{
    __shared__ float wys[Eq*Eq], whs[Eq*Eq];
    __shared__ float ht[16][Eq], ot[16][Eq];

    int b  = blockIdx.y;
    int s0 = blockIdx.x * 16;
    int tid = threadIdx.x;

    for (int i = tid; i < Eq*Eq; i += 256) { wys[i] = wy[i]; whs[i] = wh[i]; }
    for (int i = tid; i < 16*Eq; i += 256) {
        int s = i >> 6, k = i & 63;
        ht[s][k] = g_h1 [(b*Sq + s0 + s)*Eq + k];
        ot[s][k] = g_out[(b*Sq + s0 + s)*Eq + k];
    }
    __syncthreads();

    int sl = tid >> 4;
    int e0 = (tid & 15) * 4;
    float acc[4] = {0.f, 0.f, 0.f, 0.f};
#pragma unroll 8
    for (int k = 0; k < Eq; k++) {
        float hv = ht[sl][k], ov = ot[sl][k];
#pragma unroll
        for (int u = 0; u < 4; u++)
            acc[u] += hv*wys[k*Eq + e0 + u] + ov*whs[k*Eq + e0 + u];
    }
    float* dst = &g_base[(b*Sq + s0 + sl)*Eq + e0];
#pragma unroll
    for (int u = 0; u < 4; u++) dst[u] = acc[u];
}

// ---------------------------------------------------------------------------
// Attention scan: one CTA per b, 384 threads (one per s).
// Tb = tanh(base) precomputed once; per step
//   tanh(base+rwr) = (Tb + tr)/(1 + Tb*tr),  tr = tanh(rwr)  (exact identity)
// wr/wt columns live in registers of threads 0..127.
// ---------------------------------------------------------------------------
#define ATT_FLOATS (2*Sq*ST + 4*64 + 2*Sq + 12*64 + 16)
#define ATT_SMEM   (ATT_FLOATS*4)

__global__ __launch_bounds__(384) void attn_kernel(
    const float* __restrict__ wvec, const float* __restrict__ wr,
    const float* __restrict__ wt,   const float* __restrict__ s1s)
{
    extern __shared__ float sm[];
    float* Tb_s   = sm;                    // Sq*ST  tanh(base), stride 68
    float* h_sm   = Tb_s + Sq*ST;          // Sq*ST
    float* r_s    = h_sm + Sq*ST;          // 64
    float* tr_s   = r_s + 64;              // 64  tanh(r@wr)
    float* trwt_s = tr_s + 64;             // 64  tanh(r@wt)
    float* w_s    = trwt_s + 64;           // 64
    float* s1s_s  = w_s + 64;              // Sq
    float* p_s    = s1s_s + Sq;            // Sq
    float* part   = p_s + Sq;              // 12*64
    float* red    = part + 12*64;          // 16

    int b = blockIdx.x, tid = threadIdx.x;
    int lane = tid & 31, wid = tid >> 5;

    // register-resident wr/wt column (threads 0..127)
    float wcol[64];
    if (tid < 128) {
        const float* wsrc = (tid < 64) ? (wr + tid) : (wt + tid - 64);
#pragma unroll
        for (int k = 0; k < 64; k++) wcol[k] = wsrc[k*Eq];
    }

    for (int i = tid; i < Sq*Eq; i += 384) {
        int s = i >> 6, e = i & 63;
        Tb_s[s*ST + e] = ftanh(g_base[b*Sq*Eq + i]);
        h_sm[s*ST + e] = g_h1 [b*Sq*Eq + i];
    }
    if (tid < 64) { r_s[tid] = 0.f; w_s[tid] = wvec[tid]; }
    s1s_s[tid] = s1s[b*Sq + tid];
    __syncthreads();

    for (int t = 0; t < Sq; t++) {
        // phase1: tr = tanh(r@wr), trwt = tanh(r@wt)
        if (tid < 128) {
            const float4* r4 = (const float4*)r_s;
            float a0 = 0.f, a1 = 0.f;
#pragma unroll
            for (int q = 0; q < 16; q += 2) {
                float4 v0 = r4[q], v1 = r4[q+1];
                a0 += wcol[4*q  ]*v0.x + wcol[4*q+1]*v0.y
                    + wcol[4*q+2]*v0.z + wcol[4*q+3]*v0.w;
                a1 += wcol[4*q+4]*v1.x + wcol[4*q+5]*v1.y
                    + wcol[4*q+6]*v1.z + wcol[4*q+7]*v1.w;
            }
            float v = ftanh(a0 + a1);
            if (tid < 64) tr_s[tid] = v; else trwt_s[tid-64] = v;
        }
        __syncthreads();

        // phase2: score via tanh addition identity; row s = tid
        {
            const float4* tb4 = (const float4*)&Tb_s[tid*ST];
            const float4* tr4 = (const float4*)tr_s;
            const float4* w4  = (const float4*)w_s;
            float sc = 0.f;
#pragma unroll
            for (int q = 0; q < 16; q++) {
                float4 tb = tb4[q], tr = tr4[q], wv = w4[q];
                sc += wv.x*(tb.x+tr.x)*rcp_fast(fmaf(tb.x,tr.x,1.f));
                sc += wv.y*(tb.y+tr.y)*rcp_fast(fmaf(tb.y,tr.y,1.f));
                sc += wv.z*(tb.z+tr.z)*rcp_fast(fmaf(tb.z,tr.z,1.f));
                sc += wv.w*(tb.w+tr.w)*rcp_fast(fmaf(tb.w,tr.w,1.f));
            }
            float m1 = s1s_s[tid];
            sc = m1*sc - (1.f - m1)*1e12f;
            float p = __expf(sc);
            p_s[tid] = p;
            float v = p;
#pragma unroll
            for (int o = 16; o > 0; o >>= 1) v += __shfl_xor_sync(0xffffffffu, v, o);
            if (lane == 0) red[wid] = v;
        }
        __syncthreads();

        // phase3: partial h.p sums (12 groups of 32 s, float2 over e)
        {
            int e2 = (lane) * 2;               // 0..62
            int sb = wid * 32;
            float a0 = 0.f, a1 = 0.f;
#pragma unroll 8
            for (int si = 0; si < 32; si++) {
                float p = p_s[sb + si];
                float2 hv = *(const float2*)&h_sm[(sb+si)*ST + e2];
                a0 += hv.x * p; a1 += hv.y * p;
            }
            part[wid*64 + e2]     = a0;
            part[wid*64 + e2 + 1] = a1;
            if (tid == 0) {
                float s = 0.f;
#pragma unroll
                for (int i = 0; i < 12; i++) s += red[i];
                red[12] = rcp_fast(s);
            }
        }
        __syncthreads();

        // phase4: r_new
        if (tid < 64) {
            float invden = red[12];
            float a = 0.f;
#pragma unroll
            for (int g = 0; g < 12; g++) a += part[g*64 + tid];
            float rn = a*invden + trwt_s[tid];
            r_s[tid] = rn;
            g_Rt[(b*Sq + t)*Eq + tid] = rn;
        }
        __syncthreads();
    }
}

// ---------------------------------------------------------------------------
// Final gathers + MLP head
// ---------------------------------------------------------------------------
__global__ __launch_bounds__(128) void final_kernel(
    const int* __restrict__ s2len,
    const float* __restrict__ wp, const float* __restrict__ wx,
    const float* __restrict__ l1W, const float* __restrict__ l1b,
    const float* __restrict__ lW,  const float* __restrict__ lb,
    float* __restrict__ outp)
{
    __shared__ float rn[64], hn[64], hid[64], h2[128];
    int b = blockIdx.x, tid = threadIdx.x;

    if (tid < 64) {
        int idx = s2len[b*64 + tid];
        rn[tid] = g_Rt [(b*Sq + idx)*Eq + tid];
        hn[tid] = g_out[(b*Sq + idx)*Eq + tid];
    }
    __syncthreads();
    if (tid < 64) {
        float a = 0.f;
#pragma unroll 8
        for (int e = 0; e < 64; e++)
            a += rn[e]*wp[e*64 + tid] + hn[e]*wx[e*64 + tid];
        hid[tid] = ftanh(a);
    }
    __syncthreads();
    {
        float a = l1b[tid];
#pragma unroll 8
        for (int f = 0; f < 64; f++) a += hid[f]*l1W[tid*64 + f];
        h2[tid] = ftanh(a);
    }
    __syncthreads();
    if (tid < 4) {
        float a = lb[tid];
#pragma unroll 8
        for (int j = 0; j < 128; j++) a += h2[j]*lW[tid*128 + j];
        outp[b*4 + tid] = a;
    }
}

// ---------------------------------------------------------------------------
extern "C" void kernel_launch(void* const* d_in, const int* in_sizes, int n_in,
                              void* d_out, int out_size)
{
    (void)in_sizes; (void)n_in; (void)out_size;

    const int*   s1   = (const int*)d_in[0];
    const int*   s2   = (const int*)d_in[1];
    const int*   s1l  = (const int*)d_in[2];
    const int*   s2l  = (const int*)d_in[3];
    const float* s1s  = (const float*)d_in[4];
    /* d_in[5] = s2_s, unused by the reference */
    const float* emb  = (const float*)d_in[6];
    const float* Wih1 = (const float*)d_in[7];
    const float* Whh1 = (const float*)d_in[8];
    const float* bih1 = (const float*)d_in[9];
    const float* bhh1 = (const float*)d_in[10];
    const float* Wih2 = (const float*)d_in[11];
    const float* Whh2 = (const float*)d_in[12];
    const float* bih2 = (const float*)d_in[13];
    const float* bhh2 = (const float*)d_in[14];
    const float* wy   = (const float*)d_in[15];
    const float* wh   = (const float*)d_in[16];
    const float* wv   = (const float*)d_in[17];
    const float* wp   = (const float*)d_in[18];
    const float* wx   = (const float*)d_in[19];
    const float* wr   = (const float*)d_in[20];
    const float* wt   = (const float*)d_in[21];
    const float* l1W  = (const float*)d_in[22];
    const float* l1b  = (const float*)d_in[23];
    const float* lW   = (const float*)d_in[24];
    const float* lb   = (const float*)d_in[25];
    float* outp = (float*)d_out;

    cudaFuncSetAttribute(attn_kernel,
                         cudaFuncAttributeMaxDynamicSharedMemorySize, ATT_SMEM);

    float* xp1; cudaGetSymbolAddress((void**)&xp1, g_xp1);
    float* xp2; cudaGetSymbolAddress((void**)&xp2, g_xp2);

    xproj_kernel<<<(Bq*Sq)/32, 256>>>(s1, emb, Wih1, bih1, bhh1, xp1);
    xproj_kernel<<<(Bq*Sq)/32, 256>>>(s2, emb, Wih2, bih2, bhh2, xp2);
    lstm_kernel<<<Bq, 512>>>(xp1, Whh1, nullptr, 0);
    lstm_kernel<<<Bq, 512>>>(xp2, Whh2, s1l, 1);
    base_kernel<<<dim3(24, Bq), 256>>>(wy, wh);
    attn_kernel<<<Bq, 384, ATT_SMEM>>>(wv, wr, wt, s1s);
    final_kernel<<<Bq, 128>>>(s2l, wp, wx, l1W, l1b, lW, lb, outp);
}

// round 5
// speedup vs baseline: 1.9216x; 1.1663x over previous
#include <cuda_runtime.h>
#include <cstdint>
#include <math.h>

#define Bq 64
#define Sq 384
#define Eq 64
#define Dq 50
#define Gq 256   // 4*E
#define ST 68    // smem row stride (16B-aligned rows, conflict-free)
#define SL 192   // attention rows per cluster CTA (Sq/2)

// scratch (allocation-free rule: __device__ globals)
__device__ float g_h1[Bq*Sq*Eq];
__device__ float g_c1[Bq*Sq*Eq];
__device__ float g_out[Bq*Sq*Eq];
__device__ float g_base[Bq*Sq*Eq];
__device__ float g_Rt[Bq*Sq*Eq];
__device__ float g_xp1[Bq*Sq*Gq];
__device__ float g_xp2[Bq*Sq*Gq];

// ---- fast transcendentals (err ~1e-6, well under the 1e-3 gate) ----------
__device__ __forceinline__ float rcp_fast(float x){
    float r; asm("rcp.approx.f32 %0, %1;" : "=f"(r) : "f"(x)); return r;
}
__device__ __forceinline__ float ftanh(float x){
    float t = __expf(-2.f * fabsf(x));
    float y = (1.f - t) * rcp_fast(1.f + t);
    return copysignf(y, x);
}
__device__ __forceinline__ float fsig(float x){
    return rcp_fast(1.f + __expf(-x));
}
__device__ __forceinline__ uint32_t smem_u32(const void* p){
    uint32_t a;
    asm("{ .reg .u64 t; cvta.to.shared.u64 t, %1; cvt.u32.u64 %0, t; }"
        : "=r"(a) : "l"(p));
    return a;
}
__device__ __forceinline__ uint32_t mapa_u32(uint32_t addr, uint32_t rank){
    uint32_t r;
    asm("mapa.shared::cluster.u32 %0, %1, %2;" : "=r"(r) : "r"(addr), "r"(rank));
    return r;
}
__device__ __forceinline__ float ld_cluster_f32(uint32_t addr){
    float v;
    asm volatile("ld.shared::cluster.f32 %0, [%1];" : "=f"(v) : "r"(addr));
    return v;
}
__device__ __forceinline__ void cluster_sync(){
    asm volatile("barrier.cluster.arrive.aligned;" ::: "memory");
    asm volatile("barrier.cluster.wait.aligned;"   ::: "memory");
}

// ---------------------------------------------------------------------------
// Input projection: xp[b,s,g] = emb[tok[b,s]] @ Wih[g,:] + bih[g] + bhh[g]
// ---------------------------------------------------------------------------
__global__ __launch_bounds__(256) void xproj_kernel(
    const int* __restrict__ toks, const float* __restrict__ emb,
    const float* __restrict__ Wih, const float* __restrict__ bih,
    const float* __restrict__ bhh, float* __restrict__ xp)
{
    __shared__ float xs[32][Dq];
    __shared__ int   tk[32];
    int row0 = blockIdx.x * 32;
    int j = threadIdx.x;

    if (j < 32) tk[j] = toks[row0 + j];
    __syncthreads();
    for (int i = j; i < 32*Dq; i += 256) {
        int r = i / Dq, k = i % Dq;
        xs[r][k] = emb[tk[r]*Dq + k];
    }

    float w[Dq];
#pragma unroll
    for (int k = 0; k < Dq; k++) w[k] = Wih[j*Dq + k];
    float bias = bih[j] + bhh[j];
    __syncthreads();

#pragma unroll 4
    for (int r = 0; r < 32; r++) {
        float acc = bias;
#pragma unroll
        for (int k = 0; k < Dq; k++) acc += w[k]*xs[r][k];
        xp[(row0 + r)*Gq + j] = acc;
    }
}

// ---------------------------------------------------------------------------
// Recurrent LSTM (R2 shape): one CTA per b, 256 threads (one per gate).
// ---------------------------------------------------------------------------
__global__ __launch_bounds__(256) void lstm_kernel(
    const float* __restrict__ xp, const float* __restrict__ Whh,
    const int* __restrict__ iidx, int mode)
{
    __shared__ __align__(16) float hs[Eq];
    __shared__ float gs[Gq];

    int b = blockIdx.x, j = threadIdx.x;
    float* oh = mode ? g_out : g_h1;
    float* oc = mode ? nullptr : g_c1;

    float whh[Eq];
#pragma unroll
    for (int k = 0; k < Eq; k++) whh[k] = Whh[j*Eq + k];

    float c = 0.f;
    if (j < Eq) {
        float h0 = 0.f;
        if (mode) {
            int idx = iidx[b*Eq + j];          // s1_len is (B,1,E)
            h0 = g_h1[(b*Sq + idx)*Eq + j];
            c  = g_c1[(b*Sq + idx)*Eq + j];
        }
        hs[j] = h0;
    }
    __syncthreads();

    const float* xpb = xp + (size_t)b*Sq*Gq + j;
    float xv = xpb[0];

    for (int t = 0; t < Sq; t++) {
        float acc = xv;
        const float4* h4 = (const float4*)hs;
#pragma unroll
        for (int k = 0; k < Eq/4; k++) {
            float4 hv = h4[k];
            acc += whh[4*k]*hv.x + whh[4*k+1]*hv.y
                 + whh[4*k+2]*hv.z + whh[4*k+3]*hv.w;
        }
        if (t + 1 < Sq) xv = xpb[(t+1)*Gq];    // prefetch next gate input
        gs[j] = acc;
        __syncthreads();

        if (j < Eq) {
            float ig = fsig(gs[j]);
            float fg = fsig(gs[Eq + j]);
            float gg = ftanh(gs[2*Eq + j]);
            float og = fsig(gs[3*Eq + j]);
            c = fg*c + ig*gg;
            float h = og*ftanh(c);
            hs[j] = h;
            oh[(b*Sq + t)*Eq + j] = h;
            if (oc) oc[(b*Sq + t)*Eq + j] = c;
        }
        __syncthreads();
    }
}

// ---------------------------------------------------------------------------
// base[b,s,:] = h1[b,s,:] @ wy + out[b,s,:] @ wh
// ---------------------------------------------------------------------------
__global__ __launch_bounds__(256) void base_kernel(
    const float* __restrict__ wy, const float* __restrict__ wh)
{
    __shared__ float wys[Eq*Eq], whs[Eq*Eq];
    __shared__ float ht[16][Eq], ot[16][Eq];

    int b  = blockIdx.y;
    int s0 = blockIdx.x * 16;
    int tid = threadIdx.x;

    for (int i = tid; i < Eq*Eq; i += 256) { wys[i] = wy[i]; whs[i] = wh[i]; }
    for (int i = tid; i < 16*Eq; i += 256) {
        int s = i >> 6, k = i & 63;
        ht[s][k] = g_h1 [(b*Sq + s0 + s)*Eq + k];
        ot[s][k] = g_out[(b*Sq + s0 + s)*Eq + k];
    }
    __syncthreads();

    int sl = tid >> 4;
    int e0 = (tid & 15) * 4;
    float acc[4] = {0.f, 0.f, 0.f, 0.f};
#pragma unroll 8
    for (int k = 0; k < Eq; k++) {
        float hv = ht[sl][k], ov = ot[sl][k];
#pragma unroll
        for (int u = 0; u < 4; u++)
            acc[u] += hv*wys[k*Eq + e0 + u] + ov*whs[k*Eq + e0 + u];
    }
    float* dst = &g_base[(b*Sq + s0 + sl)*Eq + e0];
#pragma unroll
    for (int u = 0; u < 4; u++) dst[u] = acc[u];
}

// ---------------------------------------------------------------------------
// Attention scan, 2-CTA cluster per batch row: rank r owns s in [r*192,+192).
// Per step each CTA computes partial softmax sums, exchanges (num[64], sum_p)
// via DSMEM after one barrier.cluster; both reconstruct bit-identical r.
//   tanh(base+rwr) = (Tb + tr)/(1 + Tb*tr),  Tb = tanh(base) precomputed.
// ---------------------------------------------------------------------------
#define ATT_FLOATS (2*SL*ST + 4*64 + 2*SL + 12*64 + 8 + 2*66)
#define ATT_SMEM   (ATT_FLOATS*4)

__global__ __launch_bounds__(384) __cluster_dims__(2, 1, 1)
void attn_kernel(
    const float* __restrict__ wvec, const float* __restrict__ wr,
    const float* __restrict__ wt,   const float* __restrict__ s1s)
{
    extern __shared__ float sm[];
    float* Tb_s   = sm;                    // SL*ST  tanh(base)
    float* h_sm   = Tb_s + SL*ST;          // SL*ST
    float* r_s    = h_sm + SL*ST;          // 64
    float* tr_s   = r_s + 64;              // 64
    float* trwt_s = tr_s + 64;             // 64
    float* w_s    = trwt_s + 64;           // 64
    float* s1s_s  = w_s + 64;              // SL
    float* p_s    = s1s_s + SL;            // SL
    float* part   = p_s + SL;              // 12*64
    float* red    = part + 12*64;          // 8
    float* expb   = red + 8;               // 2*66 export slots

    int cta  = blockIdx.x;
    int b    = cta >> 1;
    uint32_t rank = cta & 1u;
    int tid  = threadIdx.x;
    int lane = tid & 31, wid = tid >> 5;

    uint32_t exp_local = smem_u32(expb);
    uint32_t exp_peer  = mapa_u32(exp_local, rank ^ 1u);

    // register-resident wr/wt column (threads 0..127)
    float wcol[64];
    if (tid < 128) {
        const float* wsrc = (tid < 64) ? (wr + tid) : (wt + tid - 64);
#pragma unroll
        for (int k = 0; k < 64; k++) wcol[k] = wsrc[k*Eq];
    }

    const int gofs = b*Sq*Eq + (int)rank*SL*Eq;
    for (int i = tid; i < SL*Eq; i += 384) {
        int s = i >> 6, e = i & 63;
        Tb_s[s*ST + e] = ftanh(g_base[gofs + i]);
        h_sm[s*ST + e] = g_h1 [gofs + i];
    }
    if (tid < 64) { r_s[tid] = 0.f; w_s[tid] = wvec[tid]; }
    if (tid < SL) s1s_s[tid] = s1s[b*Sq + (int)rank*SL + tid];
    __syncthreads();

    for (int t = 0; t < Sq; t++) {
        int pb = (t & 1) * 66;

        // p1: tr = tanh(r@wr), trwt = tanh(r@wt)   (threads 0..127)
        if (tid < 128) {
            const float4* r4 = (const float4*)r_s;
            float a0 = 0.f, a1 = 0.f;
#pragma unroll
            for (int q = 0; q < 16; q += 2) {
                float4 v0 = r4[q], v1 = r4[q+1];
                a0 += wcol[4*q  ]*v0.x + wcol[4*q+1]*v0.y
                    + wcol[4*q+2]*v0.z + wcol[4*q+3]*v0.w;
                a1 += wcol[4*q+4]*v1.x + wcol[4*q+5]*v1.y
                    + wcol[4*q+6]*v1.z + wcol[4*q+7]*v1.w;
            }
            float v = ftanh(a0 + a1);
            if (tid < 64) tr_s[tid] = v; else trwt_s[tid-64] = v;
        }
        __syncthreads();

        // p2: score row tid (tid < 192), tanh addition identity
        if (tid < SL) {
            const float4* tb4 = (const float4*)&Tb_s[tid*ST];
            const float4* tr4 = (const float4*)tr_s;
            const float4* w4  = (const float4*)w_s;
            float sc = 0.f;
#pragma unroll
            for (int q = 0; q < 16; q++) {
                float4 tb = tb4[q], tr = tr4[q], wv = w4[q];
                sc += wv.x*(tb.x+tr.x)*rcp_fast(fmaf(tb.x,tr.x,1.f));
                sc += wv.y*(tb.y+tr.y)*rcp_fast(fmaf(tb.y,tr.y,1.f));
                sc += wv.z*(tb.z+tr.z)*rcp_fast(fmaf(tb.z,tr.z,1.f));
                sc += wv.w*(tb.w+tr.w)*rcp_fast(fmaf(tb.w,tr.w,1.f));
            }
            float m1 = s1s_s[tid];
            sc = m1*sc - (1.f - m1)*1e12f;
            float p = __expf(sc);
            p_s[tid] = p;
            float v = p;
#pragma unroll
            for (int o = 16; o > 0; o >>= 1) v += __shfl_xor_sync(0xffffffffu, v, o);
            if (lane == 0) red[wid] = v;   // wid 0..5
        }
        __syncthreads();

        // p3: h.p partials — 12 warps x 16 rows; lane covers 2 e-columns
        {
            int e2 = lane * 2;
            int sb = wid * 16;
            float a0 = 0.f, a1 = 0.f;
#pragma unroll
            for (int si = 0; si < 16; si++) {
                float p = p_s[sb + si];
                float2 hv = *(const float2*)&h_sm[(sb+si)*ST + e2];
                a0 += hv.x * p; a1 += hv.y * p;
            }
            part[wid*64 + e2]     = a0;
            part[wid*64 + e2 + 1] = a1;
            if (tid == 0) {
                float s = 0.f;
#pragma unroll
                for (int i = 0; i < 6; i++) s += red[i];
                expb[pb + 64] = s;            // local sum_p export
            }
        }
        __syncthreads();

        // p4: local numerator export
        float num_local = 0.f;
        if (tid < 64) {
#pragma unroll
            for (int g = 0; g < 12; g++) num_local += part[g*64 + tid];
            expb[pb + tid] = num_local;
        }
        cluster_sync();

        // p5: combine with peer partials, update r (bit-identical on both CTAs)
        if (tid < 64) {
            float sl_ = 0.f;
#pragma unroll
            for (int i = 0; i < 6; i++) sl_ += red[i];
            float pn = ld_cluster_f32(exp_peer + (pb + tid)*4);
            float ps = ld_cluster_f32(exp_peer + (pb + 64)*4);
            float num  = num_local + pn;
            float sump = sl_ + ps;
            float rn = num*rcp_fast(sump) + trwt_s[tid];
            r_s[tid] = rn;
            if (rank == 0) g_Rt[(b*Sq + t)*Eq + tid] = rn;
        }
        __syncthreads();
    }
}

// ---------------------------------------------------------------------------
// Final gathers + MLP head
// ---------------------------------------------------------------------------
__global__ __launch_bounds__(128) void final_kernel(
    const int* __restrict__ s2len,
    const float* __restrict__ wp, const float* __restrict__ wx,
    const float* __restrict__ l1W, const float* __restrict__ l1b,
    const float* __restrict__ lW,  const float* __restrict__ lb,
    float* __restrict__ outp)
{
    __shared__ float rn[64], hn[64], hid[64], h2[128];
    int b = blockIdx.x, tid = threadIdx.x;

    if (tid < 64) {
        int idx = s2len[b*64 + tid];
        rn[tid] = g_Rt [(b*Sq + idx)*Eq + tid];
        hn[tid] = g_out[(b*Sq + idx)*Eq + tid];
    }
    __syncthreads();
    if (tid < 64) {
        float a = 0.f;
#pragma unroll 8
        for (int e = 0; e < 64; e++)
            a += rn[e]*wp[e*64 + tid] + hn[e]*wx[e*64 + tid];
        hid[tid] = ftanh(a);
    }
    __syncthreads();
    {
        float a = l1b[tid];
#pragma unroll 8
        for (int f = 0; f < 64; f++) a += hid[f]*l1W[tid*64 + f];
        h2[tid] = ftanh(a);
    }
    __syncthreads();
    if (tid < 4) {
        float a = lb[tid];
#pragma unroll 8
        for (int j = 0; j < 128; j++) a += h2[j]*lW[tid*128 + j];
        outp[b*4 + tid] = a;
    }
}

// ---------------------------------------------------------------------------
extern "C" void kernel_launch(void* const* d_in, const int* in_sizes, int n_in,
                              void* d_out, int out_size)
{
    (void)in_sizes; (void)n_in; (void)out_size;

    const int*   s1   = (const int*)d_in[0];
    const int*   s2   = (const int*)d_in[1];
    const int*   s1l  = (const int*)d_in[2];
    const int*   s2l  = (const int*)d_in[3];
    const float* s1s  = (const float*)d_in[4];
    /* d_in[5] = s2_s, unused by the reference */
    const float* emb  = (const float*)d_in[6];
    const float* Wih1 = (const float*)d_in[7];
    const float* Whh1 = (const float*)d_in[8];
    const float* bih1 = (const float*)d_in[9];
    const float* bhh1 = (const float*)d_in[10];
    const float* Wih2 = (const float*)d_in[11];
    const float* Whh2 = (const float*)d_in[12];
    const float* bih2 = (const float*)d_in[13];
    const float* bhh2 = (const float*)d_in[14];
    const float* wy   = (const float*)d_in[15];
    const float* wh   = (const float*)d_in[16];
    const float* wv   = (const float*)d_in[17];
    const float* wp   = (const float*)d_in[18];
    const float* wx   = (const float*)d_in[19];
    const float* wr   = (const float*)d_in[20];
    const float* wt   = (const float*)d_in[21];
    const float* l1W  = (const float*)d_in[22];
    const float* l1b  = (const float*)d_in[23];
    const float* lW   = (const float*)d_in[24];
    const float* lb   = (const float*)d_in[25];
    float* outp = (float*)d_out;

    cudaFuncSetAttribute(attn_kernel,
                         cudaFuncAttributeMaxDynamicSharedMemorySize, ATT_SMEM);

    float* xp1; cudaGetSymbolAddress((void**)&xp1, g_xp1);
    float* xp2; cudaGetSymbolAddress((void**)&xp2, g_xp2);

    xproj_kernel<<<(Bq*Sq)/32, 256>>>(s1, emb, Wih1, bih1, bhh1, xp1);
    xproj_kernel<<<(Bq*Sq)/32, 256>>>(s2, emb, Wih2, bih2, bhh2, xp2);
    lstm_kernel<<<Bq, 256>>>(xp1, Whh1, nullptr, 0);
    lstm_kernel<<<Bq, 256>>>(xp2, Whh2, s1l, 1);
    base_kernel<<<dim3(24, Bq), 256>>>(wy, wh);
    attn_kernel<<<Bq*2, 384, ATT_SMEM>>>(wv, wr, wt, s1s);
    final_kernel<<<Bq, 128>>>(s2l, wp, wx, l1W, l1b, lW, lb, outp);
}

// round 6
// speedup vs baseline: 2.1008x; 1.0933x over previous
#include <cuda_runtime.h>
#include <cstdint>
#include <math.h>

#define Bq 64
#define Sq 384
#define Eq 64
#define Dq 50
#define Gq 256   // 4*E
#define ST 66    // smem row stride: banks 2*row%32 -> 16 rows conflict-free
#define SL 192   // attention rows per cluster CTA (Sq/2)

// scratch (allocation-free rule: __device__ globals)
__device__ float g_h1[Bq*Sq*Eq];
__device__ float g_c1[Bq*Sq*Eq];
__device__ float g_out[Bq*Sq*Eq];
__device__ float g_base[Bq*Sq*Eq];
__device__ float g_Rt[Bq*Sq*Eq];
__device__ float g_xp1[Bq*Sq*Gq];
__device__ float g_xp2[Bq*Sq*Gq];

// ---- fast transcendentals (err ~1e-6, well under the 1e-3 gate) ----------
__device__ __forceinline__ float rcp_fast(float x){
    float r; asm("rcp.approx.f32 %0, %1;" : "=f"(r) : "f"(x)); return r;
}
__device__ __forceinline__ float ftanh(float x){
    float t = __expf(-2.f * fabsf(x));
    float y = (1.f - t) * rcp_fast(1.f + t);
    return copysignf(y, x);
}
__device__ __forceinline__ float fsig(float x){
    return rcp_fast(1.f + __expf(-x));
}
__device__ __forceinline__ uint32_t smem_u32(const void* p){
    uint32_t a;
    asm("{ .reg .u64 t; cvta.to.shared.u64 t, %1; cvt.u32.u64 %0, t; }"
        : "=r"(a) : "l"(p));
    return a;
}
__device__ __forceinline__ uint32_t mapa_u32(uint32_t addr, uint32_t rank){
    uint32_t r;
    asm("mapa.shared::cluster.u32 %0, %1, %2;" : "=r"(r) : "r"(addr), "r"(rank));
    return r;
}
__device__ __forceinline__ void st_cluster_f32(uint32_t addr, float v){
    asm volatile("st.shared::cluster.f32 [%0], %1;" :: "r"(addr), "f"(v) : "memory");
}
__device__ __forceinline__ void mbar_init(uint32_t addr, uint32_t count){
    asm volatile("mbarrier.init.shared.b64 [%0], %1;" :: "r"(addr), "r"(count) : "memory");
}
__device__ __forceinline__ void mbar_arrive_remote(uint32_t addr){
    asm volatile("mbarrier.arrive.release.cluster.shared::cluster.b64 _, [%0];"
                 :: "r"(addr) : "memory");
}
__device__ __forceinline__ void mbar_wait_parity(uint32_t addr, uint32_t parity){
    uint32_t done;
    asm volatile(
        "{\n\t.reg .pred p;\n\t"
        "mbarrier.try_wait.parity.acquire.cluster.shared::cta.b64 p, [%1], %2;\n\t"
        "selp.b32 %0, 1, 0, p;\n\t}"
        : "=r"(done) : "r"(addr), "r"(parity) : "memory");
    while (!done) {
        asm volatile(
            "{\n\t.reg .pred p;\n\t"
            "mbarrier.try_wait.parity.acquire.cluster.shared::cta.b64 p, [%1], %2, 0x989680;\n\t"
            "selp.b32 %0, 1, 0, p;\n\t}"
            : "=r"(done) : "r"(addr), "r"(parity) : "memory");
    }
}
__device__ __forceinline__ void cluster_sync(){
    asm volatile("barrier.cluster.arrive.aligned;" ::: "memory");
    asm volatile("barrier.cluster.wait.aligned;"   ::: "memory");
}

// ---------------------------------------------------------------------------
// Input projection: xp[b,s,g] = emb[tok[b,s]] @ Wih[g,:] + bih[g] + bhh[g]
// ---------------------------------------------------------------------------
__global__ __launch_bounds__(256) void xproj_kernel(
    const int* __restrict__ toks, const float* __restrict__ emb,
    const float* __restrict__ Wih, const float* __restrict__ bih,
    const float* __restrict__ bhh, float* __restrict__ xp)
{
    __shared__ float xs[32][Dq];
    __shared__ int   tk[32];
    int row0 = blockIdx.x * 32;
    int j = threadIdx.x;

    if (j < 32) tk[j] = toks[row0 + j];
    __syncthreads();
    for (int i = j; i < 32*Dq; i += 256) {
        int r = i / Dq, k = i % Dq;
        xs[r][k] = emb[tk[r]*Dq + k];
    }

    float w[Dq];
#pragma unroll
    for (int k = 0; k < Dq; k++) w[k] = Wih[j*Dq + k];
    float bias = bih[j] + bhh[j];
    __syncthreads();

#pragma unroll 4
    for (int r = 0; r < 32; r++) {
        float acc = bias;
#pragma unroll
        for (int k = 0; k < Dq; k++) acc += w[k]*xs[r][k];
        xp[(row0 + r)*Gq + j] = acc;
    }
}

// ---------------------------------------------------------------------------
// Recurrent LSTM: one CTA per b, 256 threads (one per gate).
// 4 independent accumulators shorten the FMA dependency chain to ~16 deep.
// ---------------------------------------------------------------------------
__global__ __launch_bounds__(256) void lstm_kernel(
    const float* __restrict__ xp, const float* __restrict__ Whh,
    const int* __restrict__ iidx, int mode)
{
    __shared__ __align__(16) float hs[Eq];
    __shared__ float gs[Gq];

    int b = blockIdx.x, j = threadIdx.x;
    float* oh = mode ? g_out : g_h1;
    float* oc = mode ? nullptr : g_c1;

    float whh[Eq];
#pragma unroll
    for (int k = 0; k < Eq; k++) whh[k] = Whh[j*Eq + k];

    float c = 0.f;
    if (j < Eq) {
        float h0 = 0.f;
        if (mode) {
            int idx = iidx[b*Eq + j];          // s1_len is (B,1,E)
            h0 = g_h1[(b*Sq + idx)*Eq + j];
            c  = g_c1[(b*Sq + idx)*Eq + j];
        }
        hs[j] = h0;
    }
    __syncthreads();

    const float* xpb = xp + (size_t)b*Sq*Gq + j;
    float xv = xpb[0];

    for (int t = 0; t < Sq; t++) {
        const float4* h4 = (const float4*)hs;
        float a0 = xv, a1 = 0.f, a2 = 0.f, a3 = 0.f;
#pragma unroll
        for (int k = 0; k < 4; k++) {
            float4 v0 = h4[4*k], v1 = h4[4*k+1], v2 = h4[4*k+2], v3 = h4[4*k+3];
            a0 += whh[16*k   ]*v0.x + whh[16*k+1 ]*v0.y + whh[16*k+2 ]*v0.z + whh[16*k+3 ]*v0.w;
            a1 += whh[16*k+4 ]*v1.x + whh[16*k+5 ]*v1.y + whh[16*k+6 ]*v1.z + whh[16*k+7 ]*v1.w;
            a2 += whh[16*k+8 ]*v2.x + whh[16*k+9 ]*v2.y + whh[16*k+10]*v2.z + whh[16*k+11]*v2.w;
            a3 += whh[16*k+12]*v3.x + whh[16*k+13]*v3.y + whh[16*k+14]*v3.z + whh[16*k+15]*v3.w;
        }
        float acc = (a0 + a1) + (a2 + a3);
        if (t + 1 < Sq) xv = xpb[(t+1)*Gq];    // prefetch next gate input
        gs[j] = acc;
        __syncthreads();

        if (j < Eq) {
            float ig = fsig(gs[j]);
            float fg = fsig(gs[Eq + j]);
            float gg = ftanh(gs[2*Eq + j]);
            float og = fsig(gs[3*Eq + j]);
            c = fg*c + ig*gg;
            float h = og*ftanh(c);
            hs[j] = h;
            oh[(b*Sq + t)*Eq + j] = h;
            if (oc) oc[(b*Sq + t)*Eq + j] = c;
        }
        __syncthreads();
    }
}

// ---------------------------------------------------------------------------
// base[b,s,:] = h1[b,s,:] @ wy + out[b,s,:] @ wh
// ---------------------------------------------------------------------------
__global__ __launch_bounds__(256) void base_kernel(
    const float* __restrict__ wy, const float* __restrict__ wh)
{
    __shared__ float wys[Eq*Eq], whs[Eq*Eq];
    __shared__ float ht[16][Eq], ot[16][Eq];

    int b  = blockIdx.y;
    int s0 = blockIdx.x * 16;
    int tid = threadIdx.x;

    for (int i = tid; i < Eq*Eq; i += 256) { wys[i] = wy[i]; whs[i] = wh[i]; }
    for (int i = tid; i < 16*Eq; i += 256) {
        int s = i >> 6, k = i & 63;
        ht[s][k] = g_h1 [(b*Sq + s0 + s)*Eq + k];
        ot[s][k] = g_out[(b*Sq + s0 + s)*Eq + k];
    }
    __syncthreads();

    int sl = tid >> 4;
    int e0 = (tid & 15) * 4;
    float acc[4] = {0.f, 0.f, 0.f, 0.f};
#pragma unroll 8
    for (int k = 0; k < Eq; k++) {
        float hv = ht[sl][k], ov = ot[sl][k];
#pragma unroll
        for (int u = 0; u < 4; u++)
            acc[u] += hv*wys[k*Eq + e0 + u] + ov*whs[k*Eq + e0 + u];
    }
    float* dst = &g_base[(b*Sq + s0 + sl)*Eq + e0];
#pragma unroll
    for (int u = 0; u < 4; u++) dst[u] = acc[u];
}

// ---------------------------------------------------------------------------
// Attention scan, 2-CTA cluster per batch row: rank owns 192 s-rows.
// Per step: p1 (256 thr) tr/trwt gemv; p2+p3 fused across 12 warps (16 rows
// each, p in registers); partial (num,sum_p) pushed into PEER smem via
// st.shared::cluster + remote mbarrier arrive (release); local acquire-wait.
//   tanh(base+rwr) = (Tb + tr)/(1 + Tb*tr),  Tb = tanh(base) precomputed.
// ---------------------------------------------------------------------------
#define ATT_FLOATS (4 + 2*68 + 2*SL*ST + 3*64 + SL + 12*64 + 16)
#define ATT_SMEM   (ATT_FLOATS*4)

__global__ __launch_bounds__(384) __cluster_dims__(2, 1, 1)
void attn_kernel(
    const float* __restrict__ wvec, const float* __restrict__ wr,
    const float* __restrict__ wt,   const float* __restrict__ s1s)
{
    extern __shared__ float sm[];
    // sm[0..3]: mbarrier (8B) + pad
    float* imp    = sm + 4;              // 2*68 import slots (peer writes here)
    float* Tb_s   = imp + 2*68;          // SL*ST
    float* h_sm   = Tb_s + SL*ST;        // SL*ST
    float* r_s    = h_sm + SL*ST;        // 64 (16B aligned)
    float* tr_s   = r_s + 64;            // 64
    float* trwt_s = tr_s + 64;           // 64
    float* s1s_s  = trwt_s + 64;         // SL
    float* part   = s1s_s + SL;          // 12*64
    float* red    = part + 12*64;        // 16

    int cta  = blockIdx.x;
    int b    = cta >> 1;
    uint32_t rank = cta & 1u;
    int tid  = threadIdx.x;
    int lane = tid & 31, wid = tid >> 5;

    uint32_t mbar_local  = smem_u32(sm);
    uint32_t mbar_remote = mapa_u32(mbar_local, rank ^ 1u);
    uint32_t imp_remote  = mapa_u32(smem_u32(imp), rank ^ 1u);

    if (tid == 0) mbar_init(mbar_local, 64);

    // p2 weights: each thread holds its half's 32 w values
    int half = lane & 1;
    float wreg[32];
#pragma unroll
    for (int k = 0; k < 32; k++) wreg[k] = wvec[half*32 + k];

    // p1 weights: thread tid<256 -> output o=tid>>1, rows hh*32..+32
    float wcol[32];
    if (tid < 256) {
        int o = tid >> 1, hh = tid & 1;
        const float* wsrc = (o < 64) ? (wr + o) : (wt + o - 64);
#pragma unroll
        for (int k = 0; k < 32; k++) wcol[k] = wsrc[(hh*32 + k)*Eq];
    }

    const int gofs = b*Sq*Eq + (int)rank*SL*Eq;
    for (int i = tid; i < SL*Eq; i += 384) {
        int s = i >> 6, e = i & 63;
        Tb_s[s*ST + e] = ftanh(g_base[gofs + i]);
        h_sm[s*ST + e] = g_h1 [gofs + i];
    }
    if (tid < 64) r_s[tid] = 0.f;
    if (tid < SL) s1s_s[tid] = s1s[b*Sq + (int)rank*SL + tid];
    __syncthreads();
    cluster_sync();   // peer's mbarrier init visible before any remote arrive

    int row = wid*16 + (lane >> 1);      // p2 row for this thread
    const float* tbrow = &Tb_s[row*ST + half*32];
    const float* trh   = tr_s + half*32;
    float m1 = s1s_s[row];

    for (int t = 0; t < Sq; t++) {
        // p1: tr = tanh(r@wr), trwt = tanh(r@wt); 2 threads per output
        if (tid < 256) {
            int o = tid >> 1, hh = tid & 1;
            const float4* r4 = (const float4*)(r_s + hh*32);
            float a0 = 0.f, a1 = 0.f;
#pragma unroll
            for (int q = 0; q < 8; q += 2) {
                float4 v0 = r4[q], v1 = r4[q+1];
                a0 += wcol[4*q  ]*v0.x + wcol[4*q+1]*v0.y
                    + wcol[4*q+2]*v0.z + wcol[4*q+3]*v0.w;
                a1 += wcol[4*q+4]*v1.x + wcol[4*q+5]*v1.y
                    + wcol[4*q+6]*v1.z + wcol[4*q+7]*v1.w;
            }
            float s_ = a0 + a1;
            s_ += __shfl_xor_sync(0xffffffffu, s_, 1);
            if (hh == 0) {
                float v = ftanh(s_);
                if (o < 64) tr_s[o] = v; else trwt_s[o-64] = v;
            }
        }
        __syncthreads();

        // p2: score for `row` (2 threads/row, 32 elems each), identity form
        float sc = 0.f;
#pragma unroll
        for (int q = 0; q < 16; q++) {
            float2 tb = *(const float2*)&tbrow[2*q];
            float2 tr = *(const float2*)&trh[2*q];
            float d0 = rcp_fast(fmaf(tb.x, tr.x, 1.f));
            float d1 = rcp_fast(fmaf(tb.y, tr.y, 1.f));
            sc += wreg[2*q  ]*(tb.x + tr.x)*d0;
            sc += wreg[2*q+1]*(tb.y + tr.y)*d1;
        }
        sc += __shfl_xor_sync(0xffffffffu, sc, 1);
        sc = m1*sc - (1.f - m1)*1e12f;
        float p = __expf(sc);

        // warp sum of p (each p duplicated in a lane pair -> halve)
        float v = p;
#pragma unroll
        for (int o = 16; o > 0; o >>= 1) v += __shfl_xor_sync(0xffffffffu, v, o);
        if (lane == 0) red[wid] = 0.5f*v;

        // p3: h.p partials for this warp's 16 rows; lane covers 2 e-columns
        {
            int e2 = lane*2;
            float a0 = 0.f, a1 = 0.f;
            const float* hb = &h_sm[(wid*16)*ST + e2];
#pragma unroll
            for (int si = 0; si < 16; si++) {
                float pv = __shfl_sync(0xffffffffu, p, 2*si);
                float2 hv = *(const float2*)&hb[si*ST];
                a0 += hv.x * pv; a1 += hv.y * pv;
            }
            part[wid*64 + e2]     = a0;
            part[wid*64 + e2 + 1] = a1;
        }
        __syncthreads();

        // p5: combine partials, exchange with peer, update r
        if (tid < 64) {
            float nl = 0.f;
#pragma unroll
            for (int g = 0; g < 12; g++) nl += part[g*64 + tid];
            float sl_ = 0.f;
#pragma unroll
            for (int i = 0; i < 12; i++) sl_ += red[i];

            int slot = (t & 1) * 68;
            st_cluster_f32(imp_remote + (slot + tid)*4, nl);
            if (tid == 0) st_cluster_f32(imp_remote + (slot + 64)*4, sl_);
            mbar_arrive_remote(mbar_remote);           // release (64 arrivals)
            mbar_wait_parity(mbar_local, (uint32_t)(t & 1));

            float pn = imp[slot + tid];
            float ps = imp[slot + 64];
            float rn = (nl + pn)*rcp_fast(sl_ + ps) + trwt_s[tid];
            r_s[tid] = rn;
            if (rank == 0) g_Rt[(b*Sq + t)*Eq + tid] = rn;
        }
        __syncthreads();
    }
    cluster_sync();   // no CTA exits while peer may still write our smem
}

// ---------------------------------------------------------------------------
// Final gathers + MLP head
// ---------------------------------------------------------------------------
__global__ __launch_bounds__(128) void final_kernel(
    const int* __restrict__ s2len,
    const float* __restrict__ wp, const float* __restrict__ wx,
    const float* __restrict__ l1W, const float* __restrict__ l1b,
    const float* __restrict__ lW,  const float* __restrict__ lb,
    float* __restrict__ outp)
{
    __shared__ float rn[64], hn[64], hid[64], h2[128];
    int b = blockIdx.x, tid = threadIdx.x;

    if (tid < 64) {
        int idx = s2len[b*64 + tid];
        rn[tid] = g_Rt [(b*Sq + idx)*Eq + tid];
        hn[tid] = g_out[(b*Sq + idx)*Eq + tid];
    }
    __syncthreads();
    if (tid < 64) {
        float a = 0.f;
#pragma unroll 8
        for (int e = 0; e < 64; e++)
            a += rn[e]*wp[e*64 + tid] + hn[e]*wx[e*64 + tid];
        hid[tid] = ftanh(a);
    }
    __syncthreads();
    {
        float a = l1b[tid];
#pragma unroll 8
        for (int f = 0; f < 64; f++) a += hid[f]*l1W[tid*64 + f];
        h2[tid] = ftanh(a);
    }
    __syncthreads();
    if (tid < 4) {
        float a = lb[tid];
#pragma unroll 8
        for (int j = 0; j < 128; j++) a += h2[j]*lW[tid*128 + j];
        outp[b*4 + tid] = a;
    }
}

// ---------------------------------------------------------------------------
extern "C" void kernel_launch(void* const* d_in, const int* in_sizes, int n_in,
                              void* d_out, int out_size)
{
    (void)in_sizes; (void)n_in; (void)out_size;

    const int*   s1   = (const int*)d_in[0];
    const int*   s2   = (const int*)d_in[1];
    const int*   s1l  = (const int*)d_in[2];
    const int*   s2l  = (const int*)d_in[3];
    const float* s1s  = (const float*)d_in[4];
    /* d_in[5] = s2_s, unused by the reference */
    const float* emb  = (const float*)d_in[6];
    const float* Wih1 = (const float*)d_in[7];
    const float* Whh1 = (const float*)d_in[8];
    const float* bih1 = (const float*)d_in[9];
    const float* bhh1 = (const float*)d_in[10];
    const float* Wih2 = (const float*)d_in[11];
    const float* Whh2 = (const float*)d_in[12];
    const float* bih2 = (const float*)d_in[13];
    const float* bhh2 = (const float*)d_in[14];
    const float* wy   = (const float*)d_in[15];
    const float* wh   = (const float*)d_in[16];
    const float* wv   = (const float*)d_in[17];
    const float* wp   = (const float*)d_in[18];
    const float* wx   = (const float*)d_in[19];
    const float* wr   = (const float*)d_in[20];
    const float* wt   = (const float*)d_in[21];
    const float* l1W  = (const float*)d_in[22];
    const float* l1b  = (const float*)d_in[23];
    const float* lW   = (const float*)d_in[24];
    const float* lb   = (const float*)d_in[25];
    float* outp = (float*)d_out;

    cudaFuncSetAttribute(attn_kernel,
                         cudaFuncAttributeMaxDynamicSharedMemorySize, ATT_SMEM);

    float* xp1; cudaGetSymbolAddress((void**)&xp1, g_xp1);
    float* xp2; cudaGetSymbolAddress((void**)&xp2, g_xp2);

    xproj_kernel<<<(Bq*Sq)/32, 256>>>(s1, emb, Wih1, bih1, bhh1, xp1);
    xproj_kernel<<<(Bq*Sq)/32, 256>>>(s2, emb, Wih2, bih2, bhh2, xp2);
    lstm_kernel<<<Bq, 256>>>(xp1, Whh1, nullptr, 0);
    lstm_kernel<<<Bq, 256>>>(xp2, Whh2, s1l, 1);
    base_kernel<<<dim3(24, Bq), 256>>>(wy, wh);
    attn_kernel<<<Bq*2, 384, ATT_SMEM>>>(wv, wr, wt, s1s);
    final_kernel<<<Bq, 128>>>(s2l, wp, wx, l1W, l1b, lW, lb, outp);
}